// round 6
// baseline (speedup 1.0000x reference)
#include <cuda_runtime.h>
#include <cuda_bf16.h>
#include <cstdint>

// ---------------- problem constants ----------------
#define BATCH 64
#define LSEQ  1024
#define EDIM  320
#define HDIM  480
#define CDIM  32
#define NLAYER 7
#define MTOK  (BATCH*LSEQ)   // 65536

// ---------------- device scratch ----------------
__device__ float          g_bm[NLAYER*HDIM];
__device__ float          g_bias[NLAYER*HDIM];
__device__ __nv_bfloat16  g_w0[HDIM*EDIM];
__device__ __nv_bfloat16  g_wmid[(NLAYER-1)*HDIM*HDIM];
__device__ __nv_bfloat16  g_wlast[EDIM*HDIM];
__device__ float          g_xnf[(size_t)MTOK*EDIM];
__device__ __nv_bfloat16  g_xnb[(size_t)MTOK*EDIM];
__device__ __nv_bfloat16  g_tA[(size_t)MTOK*HDIM];
__device__ __nv_bfloat16  g_tB[(size_t)MTOK*HDIM];
__device__ float          g_xgf[(size_t)MTOK*EDIM];

// ---------------- small kernels ----------------

__global__ void bm_kernel(const float* __restrict__ snr,
                          const float* __restrict__ w1, const float* __restrict__ b1,
                          const float* __restrict__ w2, const float* __restrict__ b2,
                          const float* __restrict__ w3, const float* __restrict__ b3)
{
    __shared__ float h1[HDIM];
    __shared__ float h2[HDIM];
    const int j = threadIdx.x;
    const float s = snr[0];
    for (int i = 0; i < NLAYER; i++) {
        if (j < HDIM)
            h1[j] = fmaxf(0.f, s * w1[i*HDIM + j] + b1[i*HDIM + j]);
        __syncthreads();
        if (j < HDIM) {
            const float* wp = w2 + ((size_t)i*HDIM + j) * HDIM;
            float acc = b2[i*HDIM + j];
            for (int k = 0; k < HDIM; k++) acc += wp[k] * h1[k];
            h2[j] = fmaxf(0.f, acc);
        }
        __syncthreads();
        if (j < HDIM) {
            const float* wp = w3 + ((size_t)i*HDIM + j) * HDIM;
            float acc = b3[i*HDIM + j];
            for (int k = 0; k < HDIM; k++) acc += wp[k] * h2[k];
            g_bm[i*HDIM + j] = 1.f / (1.f + expf(-acc));
        }
        __syncthreads();
    }
}

__global__ void fold_row_kernel(const float* __restrict__ w, const float* __restrict__ b,
                                const float* __restrict__ bm,
                                __nv_bfloat16* __restrict__ wo, float* __restrict__ bo,
                                int rows, int cols)
{
    const int stride = gridDim.x * blockDim.x;
    const int g = blockIdx.x * blockDim.x + threadIdx.x;
    for (int idx = g; idx < rows*cols; idx += stride)
        wo[idx] = __float2bfloat16(w[idx] * bm[idx / cols]);
    for (int j = g; j < rows; j += stride)
        bo[j] = b[j] * bm[j];
}

__global__ void conv_kernel(const float* __restrict__ w, __nv_bfloat16* __restrict__ wo, int n)
{
    const int stride = gridDim.x * blockDim.x;
    for (int idx = blockIdx.x * blockDim.x + threadIdx.x; idx < n; idx += stride)
        wo[idx] = __float2bfloat16(w[idx]);
}

__global__ void ln_kernel(const float* __restrict__ x,
                          const float* __restrict__ w, const float* __restrict__ b)
{
    const int warp = threadIdx.x >> 5;
    const int lane = threadIdx.x & 31;
    const size_t t = (size_t)blockIdx.x * 8 + warp;
    const float* xp = x + t * EDIM;
    float v[10];
    float s = 0.f, s2 = 0.f;
    #pragma unroll
    for (int i = 0; i < 10; i++) {
        v[i] = xp[lane + 32*i];
        s  += v[i];
        s2 += v[i]*v[i];
    }
    #pragma unroll
    for (int o = 16; o > 0; o >>= 1) {
        s  += __shfl_xor_sync(0xffffffffu, s,  o);
        s2 += __shfl_xor_sync(0xffffffffu, s2, o);
    }
    const float mu  = s  * (1.f/EDIM);
    const float var = s2 * (1.f/EDIM) - mu*mu;
    const float inv = 1.f / sqrtf(var + 1e-5f);
    #pragma unroll
    for (int i = 0; i < 10; i++) {
        const int c = lane + 32*i;
        const float y = (v[i] - mu) * inv * w[c] + b[c];
        g_xnf[t*EDIM + c] = y;
        g_xnb[t*EDIM + c] = __float2bfloat16(y);
    }
}

// ---------------- GEMM: C[M,N] = A[M,K] @ W[N,K]^T + bias, mma.sync bf16 ----------------
#define BM_T 128
#define BK_T 32
#define LDT  (BK_T + 8)
#define STAGES 3

__device__ __forceinline__ void cp16(uint32_t s, const void* g) {
    asm volatile("cp.async.cg.shared.global [%0], [%1], 16;" :: "r"(s), "l"(g));
}
__device__ __forceinline__ void ldm4(uint32_t a, uint32_t& r0, uint32_t& r1, uint32_t& r2, uint32_t& r3) {
    asm volatile("ldmatrix.sync.aligned.m8n8.x4.shared.b16 {%0,%1,%2,%3}, [%4];"
                 : "=r"(r0), "=r"(r1), "=r"(r2), "=r"(r3) : "r"(a));
}
__device__ __forceinline__ void mma16816(float* c, const uint32_t* a, const uint32_t* b) {
    asm volatile("mma.sync.aligned.m16n8k16.row.col.f32.bf16.bf16.f32 "
                 "{%0,%1,%2,%3}, {%4,%5,%6,%7}, {%8,%9}, {%0,%1,%2,%3};"
                 : "+f"(c[0]), "+f"(c[1]), "+f"(c[2]), "+f"(c[3])
                 : "r"(a[0]), "r"(a[1]), "r"(a[2]), "r"(a[3]), "r"(b[0]), "r"(b[1]));
}

// EPI: 0 = bias -> bf16 ; 1 = sigmoid(.+bias)*xn -> fp32
template<int BN, int EPI>
__global__ __launch_bounds__(256, 2) void gemm_k(
    const __nv_bfloat16* __restrict__ A, const __nv_bfloat16* __restrict__ W,
    const float* __restrict__ bias, const float* __restrict__ xnf,
    void* __restrict__ Cout, int M, int N, int K)
{
    constexpr int NI = BN / 16;           // n8 tiles per warp (warp covers BN/2 cols)
    constexpr int ASTG = BM_T * LDT;      // elements per A stage
    constexpr int BSTG = BN * LDT;        // elements per B stage

    extern __shared__ __align__(16) __nv_bfloat16 smem[];
    __nv_bfloat16* Asm = smem;                  // [STAGES][ASTG]
    __nv_bfloat16* Bsm = smem + STAGES * ASTG;  // [STAGES][BSTG]

    const int tid  = threadIdx.x;
    const int lane = tid & 31;
    const int warp = tid >> 5;
    const int wr = warp & 3;   // 4 warps along M
    const int wc = warp >> 2;  // 2 warps along N

    const uint32_t sA = (uint32_t)__cvta_generic_to_shared(Asm);
    const uint32_t sB = (uint32_t)__cvta_generic_to_shared(Bsm);
    const size_t Arow0 = (size_t)blockIdx.x * BM_T;
    const size_t Brow0 = (size_t)blockIdx.y * BN;
    const int KT = K / BK_T;

    auto load_st = [&](int kt, int buf) {
        const __nv_bfloat16* Ag = A + Arow0 * K + (size_t)kt * BK_T;
        const uint32_t sa = sA + buf * (ASTG * 2);
        #pragma unroll 2
        for (int id = tid; id < BM_T * 4; id += 256) {
            const int r = id >> 2, c = (id & 3) * 8;
            cp16(sa + (r * LDT + c) * 2, Ag + (size_t)r * K + c);
        }
        const __nv_bfloat16* Bg = W + Brow0 * K + (size_t)kt * BK_T;
        const uint32_t sb = sB + buf * (BSTG * 2);
        #pragma unroll 2
        for (int id = tid; id < BN * 4; id += 256) {
            const int r = id >> 2, c = (id & 3) * 8;
            cp16(sb + (r * LDT + c) * 2, Bg + (size_t)r * K + c);
        }
        asm volatile("cp.async.commit_group;");
    };

    float acc[2][NI][4];
    #pragma unroll
    for (int mi = 0; mi < 2; mi++)
        #pragma unroll
        for (int ni = 0; ni < NI; ni++)
            #pragma unroll
            for (int e = 0; e < 4; e++) acc[mi][ni][e] = 0.f;

    // prologue: stages 0,1
    load_st(0, 0);
    load_st(1, 1);

    for (int kt = 0; kt < KT; kt++) {
        // ensure group kt complete (groups committed so far: min(kt+1, KT-1) beyond kt)
        if (kt < KT - 1) asm volatile("cp.async.wait_group 1;");
        else             asm volatile("cp.async.wait_group 0;");
        __syncthreads();

        // issue next load early (into buffer freed by iteration kt-1)
        if (kt + 2 < KT) load_st(kt + 2, (kt + 2) % STAGES);

        const int buf = kt % STAGES;
        const uint32_t baseA = sA + buf * (ASTG * 2);
        const uint32_t baseB = sB + buf * (BSTG * 2);
        #pragma unroll
        for (int ks = 0; ks < 2; ks++) {
            uint32_t af[2][4];
            #pragma unroll
            for (int mi = 0; mi < 2; mi++) {
                const int row = wr * 32 + mi * 16 + (lane & 15);
                const int col = ks * 16 + (lane >> 4) * 8;
                ldm4(baseA + (row * LDT + col) * 2, af[mi][0], af[mi][1], af[mi][2], af[mi][3]);
            }
            uint32_t bf[NI][2];
            #pragma unroll
            for (int np = 0; np < NI / 2; np++) {
                const int row = wc * (BN / 2) + np * 16 + (lane & 7) + ((lane >> 4) << 3);
                const int col = ks * 16 + (((lane >> 3) & 1) << 3);
                ldm4(baseB + (row * LDT + col) * 2,
                     bf[2*np][0], bf[2*np][1], bf[2*np+1][0], bf[2*np+1][1]);
            }
            #pragma unroll
            for (int mi = 0; mi < 2; mi++)
                #pragma unroll
                for (int ni = 0; ni < NI; ni++)
                    mma16816(acc[mi][ni], af[mi], bf[ni]);
        }
    }

    // epilogue
    const size_t mb = Arow0 + wr * 32;
    const int nb = (int)Brow0 + wc * (BN / 2);
    #pragma unroll
    for (int mi = 0; mi < 2; mi++) {
        #pragma unroll
        for (int ni = 0; ni < NI; ni++) {
            const size_t m0 = mb + mi * 16 + (lane >> 2);
            const int n0 = nb + ni * 8 + (lane & 3) * 2;
            #pragma unroll
            for (int e = 0; e < 4; e++) {
                const size_t m = m0 + ((e >= 2) ? 8 : 0);
                const int n = n0 + (e & 1);
                const float v = acc[mi][ni][e] + bias[n];
                if (EPI == 0) {
                    ((__nv_bfloat16*)Cout)[m * N + n] = __float2bfloat16(v);
                } else {
                    const float sg = 1.f / (1.f + __expf(-v));
                    ((float*)Cout)[m * N + n] = sg * xnf[m * N + n];
                }
            }
        }
    }
}

// ---------------- head GEMM: fp32, M=65536 N=32 K=320 ----------------
__global__ __launch_bounds__(256, 2) void head_kernel(
    const float* __restrict__ A, const float* __restrict__ W,
    const float* __restrict__ bias, float* __restrict__ out)
{
    __shared__ float ws[EDIM * CDIM];     // 40 KB
    __shared__ float as[32 * 128];        // 16 KB

    const int tid = threadIdx.x;
    for (int i = tid; i < EDIM * CDIM; i += 256) {
        const int c = i & 31;
        const int k = i >> 5;
        ws[k * CDIM + c] = W[c * EDIM + k];
    }

    const size_t row0 = (size_t)blockIdx.x * 128;
    const int rg = tid >> 3;
    const int cg = tid & 7;

    float acc[4][4];
    #pragma unroll
    for (int i = 0; i < 4; i++)
        #pragma unroll
        for (int j = 0; j < 4; j++) acc[i][j] = 0.f;

    for (int k0 = 0; k0 < EDIM; k0 += 32) {
        __syncthreads();
        #pragma unroll
        for (int i = 0; i < 4; i++) {
            const int idx = tid + 256 * i;
            const int r  = idx & 127;
            const int kq = idx >> 7;
            const float4 v = *(const float4*)(A + (row0 + r) * EDIM + k0 + kq * 4);
            as[(kq * 4 + 0) * 128 + r] = v.x;
            as[(kq * 4 + 1) * 128 + r] = v.y;
            as[(kq * 4 + 2) * 128 + r] = v.z;
            as[(kq * 4 + 3) * 128 + r] = v.w;
        }
        __syncthreads();
        #pragma unroll
        for (int k = 0; k < 32; k++) {
            const float4 av = *(const float4*)(as + k * 128 + rg * 4);
            const float4 bv = *(const float4*)(ws + (k0 + k) * CDIM + cg * 4);
            acc[0][0] += av.x * bv.x; acc[0][1] += av.x * bv.y;
            acc[0][2] += av.x * bv.z; acc[0][3] += av.x * bv.w;
            acc[1][0] += av.y * bv.x; acc[1][1] += av.y * bv.y;
            acc[1][2] += av.y * bv.z; acc[1][3] += av.y * bv.w;
            acc[2][0] += av.z * bv.x; acc[2][1] += av.z * bv.y;
            acc[2][2] += av.z * bv.z; acc[2][3] += av.z * bv.w;
            acc[3][0] += av.w * bv.x; acc[3][1] += av.w * bv.y;
            acc[3][2] += av.w * bv.z; acc[3][3] += av.w * bv.w;
        }
    }

    const float4 bv = *(const float4*)(bias + cg * 4);
    #pragma unroll
    for (int i = 0; i < 4; i++) {
        float4 o;
        o.x = acc[i][0] + bv.x;
        o.y = acc[i][1] + bv.y;
        o.z = acc[i][2] + bv.z;
        o.w = acc[i][3] + bv.w;
        *(float4*)(out + (row0 + rg * 4 + i) * CDIM + cg * 4) = o;
    }
}

// ---------------- launch ----------------
extern "C" void kernel_launch(void* const* d_in, const int* in_sizes, int n_in,
                              void* d_out, int out_size)
{
    (void)in_sizes; (void)n_in; (void)out_size;
    const float* x       = (const float*)d_in[0];
    const float* snr     = (const float*)d_in[1];
    const float* norm_w  = (const float*)d_in[2];
    const float* norm_b  = (const float*)d_in[3];
    const float* sm0_w   = (const float*)d_in[4];
    const float* sm0_b   = (const float*)d_in[5];
    const float* smm_w   = (const float*)d_in[6];
    const float* smm_b   = (const float*)d_in[7];
    const float* sml_w   = (const float*)d_in[8];
    const float* sml_b   = (const float*)d_in[9];
    const float* bm_w1   = (const float*)d_in[10];
    const float* bm_b1   = (const float*)d_in[11];
    const float* bm_w2   = (const float*)d_in[12];
    const float* bm_b2   = (const float*)d_in[13];
    const float* bm_w3   = (const float*)d_in[14];
    const float* bm_b3   = (const float*)d_in[15];
    const float* head_w  = (const float*)d_in[16];
    const float* head_b  = (const float*)d_in[17];

    float *p_bm, *p_bias, *p_xnf, *p_xgf;
    __nv_bfloat16 *p_w0, *p_wmid, *p_wlast, *p_xnb, *p_tA, *p_tB;
    cudaGetSymbolAddress((void**)&p_bm,    g_bm);
    cudaGetSymbolAddress((void**)&p_bias,  g_bias);
    cudaGetSymbolAddress((void**)&p_xnf,   g_xnf);
    cudaGetSymbolAddress((void**)&p_xgf,   g_xgf);
    cudaGetSymbolAddress((void**)&p_w0,    g_w0);
    cudaGetSymbolAddress((void**)&p_wmid,  g_wmid);
    cudaGetSymbolAddress((void**)&p_wlast, g_wlast);
    cudaGetSymbolAddress((void**)&p_xnb,   g_xnb);
    cudaGetSymbolAddress((void**)&p_tA,    g_tA);
    cudaGetSymbolAddress((void**)&p_tB,    g_tB);

    // dynamic smem: 3 stages of (128 + 160) * 40 bf16
    constexpr int SMEM_G = STAGES * (BM_T + 160) * LDT * 2;  // 69120 B
    cudaFuncSetAttribute(gemm_k<160,0>, cudaFuncAttributeMaxDynamicSharedMemorySize, SMEM_G);
    cudaFuncSetAttribute(gemm_k<160,1>, cudaFuncAttributeMaxDynamicSharedMemorySize, SMEM_G);

    // 1. gate vectors
    bm_kernel<<<1, 512>>>(snr, bm_w1, bm_b1, bm_w2, bm_b2, bm_w3, bm_b3);

    // 2. fold gates into weights (bf16), fold biases
    fold_row_kernel<<<240, 256>>>(sm0_w, sm0_b, p_bm, p_w0, p_bias, HDIM, EDIM);
    for (int i = 0; i < NLAYER - 1; i++) {
        fold_row_kernel<<<240, 256>>>(smm_w + (size_t)i*HDIM*HDIM, smm_b + i*HDIM,
                                      p_bm + (i+1)*HDIM,
                                      p_wmid + (size_t)i*HDIM*HDIM, p_bias + (i+1)*HDIM,
                                      HDIM, HDIM);
    }
    conv_kernel<<<120, 256>>>(sml_w, p_wlast, EDIM*HDIM);

    // 3. LayerNorm
    ln_kernel<<<MTOK/8, 256>>>(x, norm_w, norm_b);

    // 4. GEMM chain
    // E->H
    gemm_k<160,0><<<dim3(MTOK/BM_T, HDIM/160), 256, SMEM_G>>>(
        p_xnb, p_w0, p_bias, nullptr, p_tA, MTOK, HDIM, EDIM);
    // 6x H->H (ping-pong)
    __nv_bfloat16* bufs[2] = {p_tA, p_tB};
    for (int i = 0; i < NLAYER - 1; i++) {
        gemm_k<160,0><<<dim3(MTOK/BM_T, HDIM/160), 256, SMEM_G>>>(
            bufs[i & 1], p_wmid + (size_t)i*HDIM*HDIM, p_bias + (i+1)*HDIM, nullptr,
            bufs[(i & 1) ^ 1], MTOK, HDIM, HDIM);
    }
    // H->E with fused sigmoid * xn -> fp32 xg (chain ends in g_tA after 6 mids)
    gemm_k<160,1><<<dim3(MTOK/BM_T, EDIM/160), 256, SMEM_G>>>(
        p_tA, p_wlast, sml_b, p_xnf, p_xgf, MTOK, EDIM, HDIM);
    // head E->C, fp32
    head_kernel<<<MTOK/128, 256>>>(p_xgf, head_w, head_b, (float*)d_out);
}

// round 7
// speedup vs baseline: 1.0009x; 1.0009x over previous
#include <cuda_runtime.h>
#include <cuda_bf16.h>
#include <cstdint>

// ---------------- problem constants ----------------
#define BATCH 64
#define LSEQ  1024
#define EDIM  320
#define HDIM  480
#define CDIM  32
#define NLAYER 7
#define MTOK  (BATCH*LSEQ)   // 65536

// ---------------- device scratch ----------------
__device__ float          g_bm[NLAYER*HDIM];
__device__ float          g_bias[NLAYER*HDIM];
__device__ __nv_bfloat16  g_w0[HDIM*EDIM];
__device__ __nv_bfloat16  g_wmid[(NLAYER-1)*HDIM*HDIM];
__device__ __nv_bfloat16  g_wlast[EDIM*HDIM];
__device__ float          g_xnf[(size_t)MTOK*EDIM];
__device__ __nv_bfloat16  g_xnb[(size_t)MTOK*EDIM];
__device__ __nv_bfloat16  g_tA[(size_t)MTOK*HDIM];
__device__ __nv_bfloat16  g_tB[(size_t)MTOK*HDIM];
__device__ float          g_xgf[(size_t)MTOK*EDIM];

// ---------------- small kernels ----------------

__global__ void bm_kernel(const float* __restrict__ snr,
                          const float* __restrict__ w1, const float* __restrict__ b1,
                          const float* __restrict__ w2, const float* __restrict__ b2,
                          const float* __restrict__ w3, const float* __restrict__ b3)
{
    __shared__ float h1[HDIM];
    __shared__ float h2[HDIM];
    const int j = threadIdx.x;
    const float s = snr[0];
    for (int i = 0; i < NLAYER; i++) {
        if (j < HDIM)
            h1[j] = fmaxf(0.f, s * w1[i*HDIM + j] + b1[i*HDIM + j]);
        __syncthreads();
        if (j < HDIM) {
            const float* wp = w2 + ((size_t)i*HDIM + j) * HDIM;
            float acc = b2[i*HDIM + j];
            for (int k = 0; k < HDIM; k++) acc += wp[k] * h1[k];
            h2[j] = fmaxf(0.f, acc);
        }
        __syncthreads();
        if (j < HDIM) {
            const float* wp = w3 + ((size_t)i*HDIM + j) * HDIM;
            float acc = b3[i*HDIM + j];
            for (int k = 0; k < HDIM; k++) acc += wp[k] * h2[k];
            g_bm[i*HDIM + j] = 1.f / (1.f + expf(-acc));
        }
        __syncthreads();
    }
}

__global__ void fold_row_kernel(const float* __restrict__ w, const float* __restrict__ b,
                                const float* __restrict__ bm,
                                __nv_bfloat16* __restrict__ wo, float* __restrict__ bo,
                                int rows, int cols)
{
    const int stride = gridDim.x * blockDim.x;
    const int g = blockIdx.x * blockDim.x + threadIdx.x;
    for (int idx = g; idx < rows*cols; idx += stride)
        wo[idx] = __float2bfloat16(w[idx] * bm[idx / cols]);
    for (int j = g; j < rows; j += stride)
        bo[j] = b[j] * bm[j];
}

__global__ void conv_kernel(const float* __restrict__ w, __nv_bfloat16* __restrict__ wo, int n)
{
    const int stride = gridDim.x * blockDim.x;
    for (int idx = blockIdx.x * blockDim.x + threadIdx.x; idx < n; idx += stride)
        wo[idx] = __float2bfloat16(w[idx]);
}

__global__ void ln_kernel(const float* __restrict__ x,
                          const float* __restrict__ w, const float* __restrict__ b)
{
    const int warp = threadIdx.x >> 5;
    const int lane = threadIdx.x & 31;
    const size_t t = (size_t)blockIdx.x * 8 + warp;
    const float* xp = x + t * EDIM;
    float v[10];
    float s = 0.f, s2 = 0.f;
    #pragma unroll
    for (int i = 0; i < 10; i++) {
        v[i] = xp[lane + 32*i];
        s  += v[i];
        s2 += v[i]*v[i];
    }
    #pragma unroll
    for (int o = 16; o > 0; o >>= 1) {
        s  += __shfl_xor_sync(0xffffffffu, s,  o);
        s2 += __shfl_xor_sync(0xffffffffu, s2, o);
    }
    const float mu  = s  * (1.f/EDIM);
    const float var = s2 * (1.f/EDIM) - mu*mu;
    const float inv = 1.f / sqrtf(var + 1e-5f);
    #pragma unroll
    for (int i = 0; i < 10; i++) {
        const int c = lane + 32*i;
        const float y = (v[i] - mu) * inv * w[c] + b[c];
        g_xnf[t*EDIM + c] = y;
        g_xnb[t*EDIM + c] = __float2bfloat16(y);
    }
}

// ---------------- GEMM: C[M,N] = A[M,K] @ W[N,K]^T + bias, mma.sync bf16 ----------------
#define BM_T 128
#define BK_T 32
#define LDT  (BK_T + 8)
#define STAGES 3

__device__ __forceinline__ void cp16(uint32_t s, const void* g) {
    asm volatile("cp.async.cg.shared.global [%0], [%1], 16;" :: "r"(s), "l"(g));
}
__device__ __forceinline__ void ldm4(uint32_t a, uint32_t& r0, uint32_t& r1, uint32_t& r2, uint32_t& r3) {
    asm volatile("ldmatrix.sync.aligned.m8n8.x4.shared.b16 {%0,%1,%2,%3}, [%4];"
                 : "=r"(r0), "=r"(r1), "=r"(r2), "=r"(r3) : "r"(a));
}
__device__ __forceinline__ void mma16816(float* c, const uint32_t* a, const uint32_t* b) {
    asm volatile("mma.sync.aligned.m16n8k16.row.col.f32.bf16.bf16.f32 "
                 "{%0,%1,%2,%3}, {%4,%5,%6,%7}, {%8,%9}, {%0,%1,%2,%3};"
                 : "+f"(c[0]), "+f"(c[1]), "+f"(c[2]), "+f"(c[3])
                 : "r"(a[0]), "r"(a[1]), "r"(a[2]), "r"(a[3]), "r"(b[0]), "r"(b[1]));
}

// EPI: 0 = bias -> bf16 ; 1 = sigmoid(.+bias)*xn -> fp32
template<int BN, int EPI>
__global__ __launch_bounds__(256, 2) void gemm_k(
    const __nv_bfloat16* __restrict__ A, const __nv_bfloat16* __restrict__ W,
    const float* __restrict__ bias, const float* __restrict__ xnf,
    void* __restrict__ Cout, int M, int N, int K)
{
    constexpr int NI = BN / 16;           // n8 tiles per warp (warp covers BN/2 cols)
    constexpr int ASTG = BM_T * LDT;      // elements per A stage
    constexpr int BSTG = BN * LDT;        // elements per B stage

    extern __shared__ __align__(16) __nv_bfloat16 smem[];
    __nv_bfloat16* Asm = smem;                  // [STAGES][ASTG]
    __nv_bfloat16* Bsm = smem + STAGES * ASTG;  // [STAGES][BSTG]

    const int tid  = threadIdx.x;
    const int lane = tid & 31;
    const int warp = tid >> 5;
    const int wr = warp & 3;   // 4 warps along M
    const int wc = warp >> 2;  // 2 warps along N

    const uint32_t sA = (uint32_t)__cvta_generic_to_shared(Asm);
    const uint32_t sB = (uint32_t)__cvta_generic_to_shared(Bsm);
    const size_t Arow0 = (size_t)blockIdx.x * BM_T;
    const size_t Brow0 = (size_t)blockIdx.y * BN;
    const int KT = K / BK_T;

    auto load_st = [&](int kt, int buf) {
        const __nv_bfloat16* Ag = A + Arow0 * K + (size_t)kt * BK_T;
        const uint32_t sa = sA + buf * (ASTG * 2);
        #pragma unroll 2
        for (int id = tid; id < BM_T * 4; id += 256) {
            const int r = id >> 2, c = (id & 3) * 8;
            cp16(sa + (r * LDT + c) * 2, Ag + (size_t)r * K + c);
        }
        const __nv_bfloat16* Bg = W + Brow0 * K + (size_t)kt * BK_T;
        const uint32_t sb = sB + buf * (BSTG * 2);
        #pragma unroll 2
        for (int id = tid; id < BN * 4; id += 256) {
            const int r = id >> 2, c = (id & 3) * 8;
            cp16(sb + (r * LDT + c) * 2, Bg + (size_t)r * K + c);
        }
        asm volatile("cp.async.commit_group;");
    };

    float acc[2][NI][4];
    #pragma unroll
    for (int mi = 0; mi < 2; mi++)
        #pragma unroll
        for (int ni = 0; ni < NI; ni++)
            #pragma unroll
            for (int e = 0; e < 4; e++) acc[mi][ni][e] = 0.f;

    // prologue: stages 0,1
    load_st(0, 0);
    load_st(1, 1);

    for (int kt = 0; kt < KT; kt++) {
        // ensure group kt complete (groups committed so far: min(kt+1, KT-1) beyond kt)
        if (kt < KT - 1) asm volatile("cp.async.wait_group 1;");
        else             asm volatile("cp.async.wait_group 0;");
        __syncthreads();

        // issue next load early (into buffer freed by iteration kt-1)
        if (kt + 2 < KT) load_st(kt + 2, (kt + 2) % STAGES);

        const int buf = kt % STAGES;
        const uint32_t baseA = sA + buf * (ASTG * 2);
        const uint32_t baseB = sB + buf * (BSTG * 2);
        #pragma unroll
        for (int ks = 0; ks < 2; ks++) {
            uint32_t af[2][4];
            #pragma unroll
            for (int mi = 0; mi < 2; mi++) {
                const int row = wr * 32 + mi * 16 + (lane & 15);
                const int col = ks * 16 + (lane >> 4) * 8;
                ldm4(baseA + (row * LDT + col) * 2, af[mi][0], af[mi][1], af[mi][2], af[mi][3]);
            }
            uint32_t bf[NI][2];
            #pragma unroll
            for (int np = 0; np < NI / 2; np++) {
                const int row = wc * (BN / 2) + np * 16 + (lane & 7) + ((lane >> 4) << 3);
                const int col = ks * 16 + (((lane >> 3) & 1) << 3);
                ldm4(baseB + (row * LDT + col) * 2,
                     bf[2*np][0], bf[2*np][1], bf[2*np+1][0], bf[2*np+1][1]);
            }
            #pragma unroll
            for (int mi = 0; mi < 2; mi++)
                #pragma unroll
                for (int ni = 0; ni < NI; ni++)
                    mma16816(acc[mi][ni], af[mi], bf[ni]);
        }
    }

    // epilogue
    const size_t mb = Arow0 + wr * 32;
    const int nb = (int)Brow0 + wc * (BN / 2);
    #pragma unroll
    for (int mi = 0; mi < 2; mi++) {
        #pragma unroll
        for (int ni = 0; ni < NI; ni++) {
            const size_t m0 = mb + mi * 16 + (lane >> 2);
            const int n0 = nb + ni * 8 + (lane & 3) * 2;
            #pragma unroll
            for (int e = 0; e < 4; e++) {
                const size_t m = m0 + ((e >= 2) ? 8 : 0);
                const int n = n0 + (e & 1);
                const float v = acc[mi][ni][e] + bias[n];
                if (EPI == 0) {
                    ((__nv_bfloat16*)Cout)[m * N + n] = __float2bfloat16(v);
                } else {
                    const float sg = 1.f / (1.f + __expf(-v));
                    ((float*)Cout)[m * N + n] = sg * xnf[m * N + n];
                }
            }
        }
    }
}

// ---------------- head GEMM: fp32, M=65536 N=32 K=320 ----------------
__global__ __launch_bounds__(256, 2) void head_kernel(
    const float* __restrict__ A, const float* __restrict__ W,
    const float* __restrict__ bias, float* __restrict__ out)
{
    __shared__ float ws[EDIM * CDIM];     // 40 KB
    __shared__ float as[32 * 128];        // 16 KB

    const int tid = threadIdx.x;
    for (int i = tid; i < EDIM * CDIM; i += 256) {
        const int c = i & 31;
        const int k = i >> 5;
        ws[k * CDIM + c] = W[c * EDIM + k];
    }

    const size_t row0 = (size_t)blockIdx.x * 128;
    const int rg = tid >> 3;
    const int cg = tid & 7;

    float acc[4][4];
    #pragma unroll
    for (int i = 0; i < 4; i++)
        #pragma unroll
        for (int j = 0; j < 4; j++) acc[i][j] = 0.f;

    for (int k0 = 0; k0 < EDIM; k0 += 32) {
        __syncthreads();
        #pragma unroll
        for (int i = 0; i < 4; i++) {
            const int idx = tid + 256 * i;
            const int r  = idx & 127;
            const int kq = idx >> 7;
            const float4 v = *(const float4*)(A + (row0 + r) * EDIM + k0 + kq * 4);
            as[(kq * 4 + 0) * 128 + r] = v.x;
            as[(kq * 4 + 1) * 128 + r] = v.y;
            as[(kq * 4 + 2) * 128 + r] = v.z;
            as[(kq * 4 + 3) * 128 + r] = v.w;
        }
        __syncthreads();
        #pragma unroll
        for (int k = 0; k < 32; k++) {
            const float4 av = *(const float4*)(as + k * 128 + rg * 4);
            const float4 bv = *(const float4*)(ws + (k0 + k) * CDIM + cg * 4);
            acc[0][0] += av.x * bv.x; acc[0][1] += av.x * bv.y;
            acc[0][2] += av.x * bv.z; acc[0][3] += av.x * bv.w;
            acc[1][0] += av.y * bv.x; acc[1][1] += av.y * bv.y;
            acc[1][2] += av.y * bv.z; acc[1][3] += av.y * bv.w;
            acc[2][0] += av.z * bv.x; acc[2][1] += av.z * bv.y;
            acc[2][2] += av.z * bv.z; acc[2][3] += av.z * bv.w;
            acc[3][0] += av.w * bv.x; acc[3][1] += av.w * bv.y;
            acc[3][2] += av.w * bv.z; acc[3][3] += av.w * bv.w;
        }
    }

    const float4 bv = *(const float4*)(bias + cg * 4);
    #pragma unroll
    for (int i = 0; i < 4; i++) {
        float4 o;
        o.x = acc[i][0] + bv.x;
        o.y = acc[i][1] + bv.y;
        o.z = acc[i][2] + bv.z;
        o.w = acc[i][3] + bv.w;
        *(float4*)(out + (row0 + rg * 4 + i) * CDIM + cg * 4) = o;
    }
}

// ---------------- launch ----------------
extern "C" void kernel_launch(void* const* d_in, const int* in_sizes, int n_in,
                              void* d_out, int out_size)
{
    (void)in_sizes; (void)n_in; (void)out_size;
    const float* x       = (const float*)d_in[0];
    const float* snr     = (const float*)d_in[1];
    const float* norm_w  = (const float*)d_in[2];
    const float* norm_b  = (const float*)d_in[3];
    const float* sm0_w   = (const float*)d_in[4];
    const float* sm0_b   = (const float*)d_in[5];
    const float* smm_w   = (const float*)d_in[6];
    const float* smm_b   = (const float*)d_in[7];
    const float* sml_w   = (const float*)d_in[8];
    const float* sml_b   = (const float*)d_in[9];
    const float* bm_w1   = (const float*)d_in[10];
    const float* bm_b1   = (const float*)d_in[11];
    const float* bm_w2   = (const float*)d_in[12];
    const float* bm_b2   = (const float*)d_in[13];
    const float* bm_w3   = (const float*)d_in[14];
    const float* bm_b3   = (const float*)d_in[15];
    const float* head_w  = (const float*)d_in[16];
    const float* head_b  = (const float*)d_in[17];

    float *p_bm, *p_bias, *p_xnf, *p_xgf;
    __nv_bfloat16 *p_w0, *p_wmid, *p_wlast, *p_xnb, *p_tA, *p_tB;
    cudaGetSymbolAddress((void**)&p_bm,    g_bm);
    cudaGetSymbolAddress((void**)&p_bias,  g_bias);
    cudaGetSymbolAddress((void**)&p_xnf,   g_xnf);
    cudaGetSymbolAddress((void**)&p_xgf,   g_xgf);
    cudaGetSymbolAddress((void**)&p_w0,    g_w0);
    cudaGetSymbolAddress((void**)&p_wmid,  g_wmid);
    cudaGetSymbolAddress((void**)&p_wlast, g_wlast);
    cudaGetSymbolAddress((void**)&p_xnb,   g_xnb);
    cudaGetSymbolAddress((void**)&p_tA,    g_tA);
    cudaGetSymbolAddress((void**)&p_tB,    g_tB);

    // dynamic smem: 3 stages of (128 + 160) * 40 bf16
    constexpr int SMEM_G = STAGES * (BM_T + 160) * LDT * 2;  // 69120 B
    cudaFuncSetAttribute(gemm_k<160,0>, cudaFuncAttributeMaxDynamicSharedMemorySize, SMEM_G);
    cudaFuncSetAttribute(gemm_k<160,1>, cudaFuncAttributeMaxDynamicSharedMemorySize, SMEM_G);

    // 1. gate vectors
    bm_kernel<<<1, 512>>>(snr, bm_w1, bm_b1, bm_w2, bm_b2, bm_w3, bm_b3);

    // 2. fold gates into weights (bf16), fold biases
    fold_row_kernel<<<240, 256>>>(sm0_w, sm0_b, p_bm, p_w0, p_bias, HDIM, EDIM);
    for (int i = 0; i < NLAYER - 1; i++) {
        fold_row_kernel<<<240, 256>>>(smm_w + (size_t)i*HDIM*HDIM, smm_b + i*HDIM,
                                      p_bm + (i+1)*HDIM,
                                      p_wmid + (size_t)i*HDIM*HDIM, p_bias + (i+1)*HDIM,
                                      HDIM, HDIM);
    }
    conv_kernel<<<120, 256>>>(sml_w, p_wlast, EDIM*HDIM);

    // 3. LayerNorm
    ln_kernel<<<MTOK/8, 256>>>(x, norm_w, norm_b);

    // 4. GEMM chain
    // E->H
    gemm_k<160,0><<<dim3(MTOK/BM_T, HDIM/160), 256, SMEM_G>>>(
        p_xnb, p_w0, p_bias, nullptr, p_tA, MTOK, HDIM, EDIM);
    // 6x H->H (ping-pong)
    __nv_bfloat16* bufs[2] = {p_tA, p_tB};
    for (int i = 0; i < NLAYER - 1; i++) {
        gemm_k<160,0><<<dim3(MTOK/BM_T, HDIM/160), 256, SMEM_G>>>(
            bufs[i & 1], p_wmid + (size_t)i*HDIM*HDIM, p_bias + (i+1)*HDIM, nullptr,
            bufs[(i & 1) ^ 1], MTOK, HDIM, HDIM);
    }
    // H->E with fused sigmoid * xn -> fp32 xg (chain ends in g_tA after 6 mids)
    gemm_k<160,1><<<dim3(MTOK/BM_T, EDIM/160), 256, SMEM_G>>>(
        p_tA, p_wlast, sml_b, p_xnf, p_xgf, MTOK, EDIM, HDIM);
    // head E->C, fp32
    head_kernel<<<MTOK/128, 256>>>(p_xgf, head_w, head_b, (float*)d_out);
}